// round 15
// baseline (speedup 1.0000x reference)
#include <cuda_runtime.h>
#include <math.h>
#include <stdint.h>

#define MCOLS 65536
#define TCH   64
#define LRANK 8
#define NMF_ITERS 50
#define EPS_F 1.1920929e-07f
#define GRID  128                 // blocks in k_iter; stride of partials
#define IBLK  512                 // threads per k_iter block

// dynamic smem layout (bytes) for k_iter
//   sV    [0, 131072)          64 x 512 floats
//   sHnP  [131072, 147456)     4*512 ull
//   sW    [147456, 149504)     512 floats
//   sWtW  [149504, 149760)     64 floats
//   sWtWp [149760, 151808)     512 floats
//   sRed  [151808, 154112)     576 floats
#define ITER_SMEM_BYTES 154112

typedef unsigned long long ull;

// ---------------------------------------------------------------------------
// Scratch (no allocations allowed)
// ---------------------------------------------------------------------------
__device__ __align__(16) float g_V[TCH * MCOLS];          // relu(conv), row-major
__device__ __align__(16) float g_H[LRANK * MCOLS];
__device__ __align__(16) float g_Wb[2][TCH * LRANK];      // W parity buffers
__device__ __align__(16) float g_Wfin[TCH * LRANK];       // W_50 for epilogue
__device__ __align__(16) float g_partialBuf[2][576 * GRID];  // [parity][idx][block]
__device__ float g_red[256];
__device__ float g_red2[256];
__device__ unsigned g_cntE;                               // k_final last-block ticket

// PDL intrinsics guards
#if defined(__CUDA_ARCH__) && __CUDA_ARCH__ >= 900
#define GRID_DEP_SYNC() cudaGridDependencySynchronize()
#define PDL_TRIGGER()   cudaTriggerProgrammaticLaunchCompletion()
#else
#define GRID_DEP_SYNC()
#define PDL_TRIGGER()
#endif

// ---------------------------------------------------------------------------
// Packed fp32x2 helpers (per-lane bitwise identical to scalar FFMA)
// ---------------------------------------------------------------------------
__device__ __forceinline__ ull pack2(float lo, float hi) {
    ull r;
    asm("mov.b64 %0, {%1, %2};" : "=l"(r)
        : "r"(__float_as_uint(lo)), "r"(__float_as_uint(hi)));
    return r;
}
__device__ __forceinline__ void unpack2(ull v, float& lo, float& hi) {
    unsigned a, b;
    asm("mov.b64 {%0, %1}, %2;" : "=r"(a), "=r"(b) : "l"(v));
    lo = __uint_as_float(a); hi = __uint_as_float(b);
}
__device__ __forceinline__ ull fma2(ull a, ull b, ull c) {
    ull d;
    asm("fma.rn.f32x2 %0, %1, %2, %3;" : "=l"(d) : "l"(a), "l"(b), "l"(c));
    return d;
}

// ---------------------------------------------------------------------------
// Threefry-2x32 (JAX), 20 rounds
// ---------------------------------------------------------------------------
__device__ __forceinline__ void tf2x32(unsigned k0, unsigned k1,
                                       unsigned x0, unsigned x1,
                                       unsigned& o0, unsigned& o1) {
    unsigned ks2 = k0 ^ k1 ^ 0x1BD11BDAu;
    x0 += k0; x1 += k1;
#define TF_RND(r) { x0 += x1; x1 = (x1 << (r)) | (x1 >> (32 - (r))); x1 ^= x0; }
    TF_RND(13) TF_RND(15) TF_RND(26) TF_RND(6)
    x0 += k1;  x1 += ks2 + 1u;
    TF_RND(17) TF_RND(29) TF_RND(16) TF_RND(24)
    x0 += ks2; x1 += k0 + 2u;
    TF_RND(13) TF_RND(15) TF_RND(26) TF_RND(6)
    x0 += k0;  x1 += k1 + 3u;
    TF_RND(17) TF_RND(29) TF_RND(16) TF_RND(24)
    x0 += k1;  x1 += ks2 + 4u;
    TF_RND(13) TF_RND(15) TF_RND(26) TF_RND(6)
    x0 += ks2; x1 += k0 + 5u;
#undef TF_RND
    o0 = x0; o1 = x1;
}

__device__ __forceinline__ float bits_to_uniform(unsigned b) {
    return __uint_as_float((b >> 9) | 0x3f800000u) - 1.0f;
}

// ---------------------------------------------------------------------------
// K1: Vst = relu(w_pre @ eps + b_pre) + per-block sum   (proven)
// grid MUST be 256 x 256
// ---------------------------------------------------------------------------
__global__ __launch_bounds__(256) void k_preconv(const float* __restrict__ eps,
                                                 const float* __restrict__ wpre,
                                                 const float* __restrict__ bpre) {
    __shared__ __align__(16) float sT[4096];
    __shared__ float sb[64];
    __shared__ float ssum[256];
    int tid = threadIdx.x;
    for (int i = tid; i < 4096; i += 256) {
        int t = i >> 6, c = i & 63;
        sT[c * 64 + t] = wpre[i];
    }
    if (tid < 64) sb[tid] = bpre[tid];
    __syncthreads();

    int m = blockIdx.x * 256 + tid;
    float acc[64];
#pragma unroll
    for (int t = 0; t < 64; t++) acc[t] = sb[t];
#pragma unroll 1
    for (int c = 0; c < 64; c++) {
        float e = eps[c * MCOLS + m];
        const float4* wr = (const float4*)&sT[c * 64];
#pragma unroll
        for (int q = 0; q < 16; q++) {
            float4 w = wr[q];
            acc[4 * q + 0] += w.x * e;
            acc[4 * q + 1] += w.y * e;
            acc[4 * q + 2] += w.z * e;
            acc[4 * q + 3] += w.w * e;
        }
    }
    float ls = 0.f;
#pragma unroll
    for (int t = 0; t < 64; t++) {
        float v = fmaxf(acc[t], 0.f);
        g_V[t * MCOLS + m] = v;
        ls += v;
    }
    ssum[tid] = ls; __syncthreads();
    for (int s = 128; s; s >>= 1) { if (tid < s) ssum[tid] += ssum[tid + s]; __syncthreads(); }
    if (tid == 0) g_red[blockIdx.x] = ssum[0];
    __syncthreads();
    PDL_TRIGGER();
}

// ---------------------------------------------------------------------------
// K2: fused scalar+init (proven). grid MUST be 2048 x 256. W0 -> g_Wb[0].
// ---------------------------------------------------------------------------
__global__ __launch_bounds__(256) void k_init() {
    GRID_DEP_SYNC();
    __shared__ float s[256];
    __shared__ unsigned skeys[4];
    __shared__ float savg;
    int tid = threadIdx.x;
    s[tid] = g_red[tid];
    __syncthreads();
    for (int st = 128; st; st >>= 1) { if (tid < st) s[tid] += s[tid + st]; __syncthreads(); }
    if (tid == 0) {
        float mean = s[0] / (float)(TCH * MCOLS);
        savg = sqrtf(mean / (float)LRANK);
        unsigned o0, o1;
        tf2x32(0u, 0u, 0u, 0u, o0, o1); skeys[0] = o0; skeys[1] = o1;  // kW
        tf2x32(0u, 0u, 0u, 1u, o0, o1); skeys[2] = o0; skeys[3] = o1;  // kH
        if (blockIdx.x == 0) g_cntE = 0u;
    }
    __syncthreads();

    unsigned i = blockIdx.x * 256u + tid;   // < 524288
    float avg = savg;
    unsigned o0, o1;
    tf2x32(skeys[2], skeys[3], 0u, i, o0, o1);
    g_H[i] = avg * bits_to_uniform(o0 ^ o1);
    if (i < TCH * LRANK) {
        tf2x32(skeys[0], skeys[1], 0u, i, o0, o1);
        g_Wb[0][i] = avg * bits_to_uniform(o0 ^ o1);
    }
    __syncthreads();
    PDL_TRIGGER();
}

// ---------------------------------------------------------------------------
// K3: one fused NMF iteration. grid GRID=128 x IBLK=512 (1 col/thread).
//   stage: copy block's 64x512 V tile into SMEM (overlaps prologue L2 work)
//   prologue (it>0): each block redundantly reduces P_{it-1} (exact k_iterW
//     order) and computes W_it; block 0 publishes to g_Wb[(it+1)&1].
//   body: distributed WtW, packed-f32x2 H update (V from LDS),
//         packed-f32x2 partials (V from LDS).
//   Arithmetic order identical to R11/R14 -> bit-identical trajectory.
// ---------------------------------------------------------------------------
__global__ __launch_bounds__(IBLK, 1) void k_iter(int it) {
    GRID_DEP_SYNC();
    extern __shared__ __align__(16) char smraw[];
    float* sV    = (float*)smraw;                       // 64 x 512
    ull*   sHnP  = (ull*)(smraw + 131072);              // 4 x 512
    float* sW    = (float*)(smraw + 147456);            // 512
    float* sWtW  = (float*)(smraw + 149504);            // 64
    float* sWtWp = (float*)(smraw + 149760);            // 512
    float* sRed  = (float*)(smraw + 151808);            // 576

    int tid = threadIdx.x, lane = tid & 31, warp = tid >> 5;
    int bid = blockIdx.x;
    int m = bid * IBLK + tid;

    // hoist: H loads independent of W/partials
    float h[8];
#pragma unroll
    for (int l = 0; l < 8; l++) h[l] = g_H[l * MCOLS + m];

    // stage V tile into SMEM (MLP-16 batches); overlaps the prologue below
#pragma unroll 1
    for (int tb = 0; tb < 64; tb += 16) {
        float v[16];
#pragma unroll
        for (int i = 0; i < 16; i++) v[i] = g_V[(tb + i) * MCOLS + m];
#pragma unroll
        for (int i = 0; i < 16; i++) sV[(tb + i) * IBLK + tid] = v[i];
    }

    if (it > 0) {
        const float* __restrict__ P = g_partialBuf[(it + 1) & 1];  // P_{it-1}
        for (int o = tid; o < 576; o += IBLK) {
            const float4* p = (const float4*)&P[o * GRID];
            float s = 0.f;
#pragma unroll 8
            for (int b = 0; b < GRID / 4; b++) { float4 v = p[b]; s += (v.x + v.y) + (v.z + v.w); }
            sRed[o] = s;
        }
        __syncthreads();
        const float* __restrict__ Wold = g_Wb[it & 1];
        {
            int t0 = tid >> 3, l0 = tid & 7;
            float den = EPS_F;
#pragma unroll
            for (int j = 0; j < 8; j++) den += Wold[t0 * 8 + j] * sRed[512 + j * 8 + l0];
            float nw = Wold[tid] * sRed[tid] / den;
            sW[tid] = nw;
            if (bid == 0) g_Wb[(it + 1) & 1][tid] = nw;
        }
    } else {
        sW[tid] = g_Wb[0][tid];
        if (bid == 0) g_Wb[1][tid] = g_Wb[0][tid];
    }
    __syncthreads();

    // --- distributed WtW partials (8-term dot per thread) ---
    {
        int lj = tid & 63, oct = tid >> 6;            // oct in [0,8)
        int l = lj >> 3, j = lj & 7;
        float s = 0.f;
#pragma unroll
        for (int tt = 0; tt < 8; tt++) {
            int t = oct * 8 + tt;
            s += sW[t * 8 + l] * sW[t * 8 + j];
        }
        sWtWp[lj * 8 + oct] = s;
    }

    // phase 1: wtv = W^T v_col, V from SMEM (order identical to R14)
    ull wtvP[4] = {0ull, 0ull, 0ull, 0ull};
    const ull* sW2 = (const ull*)sW;                  // pairs (l, l+1) per t
#pragma unroll 8
    for (int t = 0; t < 64; t++) {
        float v = sV[t * IBLK + tid];
        ull vp = pack2(v, v);
        wtvP[0] = fma2(sW2[t * 4 + 0], vp, wtvP[0]);
        wtvP[1] = fma2(sW2[t * 4 + 1], vp, wtvP[1]);
        wtvP[2] = fma2(sW2[t * 4 + 2], vp, wtvP[2]);
        wtvP[3] = fma2(sW2[t * 4 + 3], vp, wtvP[3]);
    }
    float wtv[8];
#pragma unroll
    for (int p = 0; p < 4; p++) unpack2(wtvP[p], wtv[2 * p], wtv[2 * p + 1]);
    __syncthreads();

    // finalize WtW (64 threads, sequential octant sum)
    if (tid < 64) {
        float s = 0.f;
#pragma unroll
        for (int o = 0; o < 8; o++) s += sWtWp[tid * 8 + o];
        sWtW[tid] = s;
    }
    __syncthreads();

    // H update (scalar den, proven order)
    float hn[8];
#pragma unroll
    for (int l = 0; l < 8; l++) {
        const float4* q4 = (const float4*)&sWtW[l * 8];
        float4 qa = q4[0], qb = q4[1];
        float den = EPS_F
            + qa.x * h[0] + qa.y * h[1] + qa.z * h[2] + qa.w * h[3]
            + qb.x * h[4] + qb.y * h[5] + qb.z * h[6] + qb.w * h[7];
        hn[l] = h[l] * wtv[l] / den;
        g_H[l * MCOLS + m] = hn[l];
    }
#pragma unroll
    for (int p = 0; p < 4; p++) sHnP[p * IBLK + tid] = pack2(hn[2 * p], hn[2 * p + 1]);
    __syncthreads();

    // --- phase 2: packed partial VHt (warp: rows 4w..4w+3) + HHt (warps 0-7),
    //     V from SMEM (LDS). Accumulation order identical to R14.
    ull accP[4][4], acchP[4];
#pragma unroll
    for (int a = 0; a < 4; a++)
#pragma unroll
        for (int p = 0; p < 4; p++) accP[a][p] = 0ull;
#pragma unroll
    for (int p = 0; p < 4; p++) acchP[p] = 0ull;

    const float* sHnF = (const float*)sHnP;
#pragma unroll 4
    for (int gg = 0; gg < 16; gg++) {
        int mm = gg * 32 + lane;
        ull hlP0 = sHnP[0 * IBLK + mm];
        ull hlP1 = sHnP[1 * IBLK + mm];
        ull hlP2 = sHnP[2 * IBLK + mm];
        ull hlP3 = sHnP[3 * IBLK + mm];
        float v0 = sV[(warp * 4 + 0) * IBLK + mm];
        float v1 = sV[(warp * 4 + 1) * IBLK + mm];
        float v2 = sV[(warp * 4 + 2) * IBLK + mm];
        float v3 = sV[(warp * 4 + 3) * IBLK + mm];
        ull vp0 = pack2(v0, v0), vp1 = pack2(v1, v1);
        ull vp2 = pack2(v2, v2), vp3 = pack2(v3, v3);
        accP[0][0] = fma2(vp0, hlP0, accP[0][0]);
        accP[0][1] = fma2(vp0, hlP1, accP[0][1]);
        accP[0][2] = fma2(vp0, hlP2, accP[0][2]);
        accP[0][3] = fma2(vp0, hlP3, accP[0][3]);
        accP[1][0] = fma2(vp1, hlP0, accP[1][0]);
        accP[1][1] = fma2(vp1, hlP1, accP[1][1]);
        accP[1][2] = fma2(vp1, hlP2, accP[1][2]);
        accP[1][3] = fma2(vp1, hlP3, accP[1][3]);
        accP[2][0] = fma2(vp2, hlP0, accP[2][0]);
        accP[2][1] = fma2(vp2, hlP1, accP[2][1]);
        accP[2][2] = fma2(vp2, hlP2, accP[2][2]);
        accP[2][3] = fma2(vp2, hlP3, accP[2][3]);
        accP[3][0] = fma2(vp3, hlP0, accP[3][0]);
        accP[3][1] = fma2(vp3, hlP1, accP[3][1]);
        accP[3][2] = fma2(vp3, hlP2, accP[3][2]);
        accP[3][3] = fma2(vp3, hlP3, accP[3][3]);
        if (warp < 8) {
            float hw = sHnF[((warp >> 1) * IBLK + mm) * 2 + (warp & 1)];
            ull hwp = pack2(hw, hw);
            acchP[0] = fma2(hwp, hlP0, acchP[0]);
            acchP[1] = fma2(hwp, hlP1, acchP[1]);
            acchP[2] = fma2(hwp, hlP2, acchP[2]);
            acchP[3] = fma2(hwp, hlP3, acchP[3]);
        }
    }

    // unpack, butterfly, store partials (proven order)
    float acc[4][8], acch[8];
#pragma unroll
    for (int a = 0; a < 4; a++)
#pragma unroll
        for (int p = 0; p < 4; p++) unpack2(accP[a][p], acc[a][2 * p], acc[a][2 * p + 1]);
#pragma unroll
    for (int p = 0; p < 4; p++) unpack2(acchP[p], acch[2 * p], acch[2 * p + 1]);

    float* __restrict__ pbufW = g_partialBuf[it & 1];
#pragma unroll
    for (int a = 0; a < 4; a++)
#pragma unroll
        for (int l = 0; l < 8; l++) {
            float x = acc[a][l];
#pragma unroll
            for (int s = 16; s; s >>= 1) x += __shfl_xor_sync(0xffffffffu, x, s);
            acc[a][l] = x;
        }
#pragma unroll
    for (int l = 0; l < 8; l++) {
        float x = acch[l];
#pragma unroll
        for (int s = 16; s; s >>= 1) x += __shfl_xor_sync(0xffffffffu, x, s);
        acch[l] = x;
    }
    if (lane == 0) {
#pragma unroll
        for (int tt = 0; tt < 4; tt++)
#pragma unroll
            for (int l = 0; l < 8; l++)
                pbufW[((warp * 4 + tt) * 8 + l) * GRID + bid] = acc[tt][l];
        if (warp < 8) {
#pragma unroll
            for (int l = 0; l < 8; l++)
                pbufW[(512 + warp * 8 + l) * GRID + bid] = acch[l];
        }
    }
    __syncthreads();
    PDL_TRIGGER();
}

// ---------------------------------------------------------------------------
// K4: final W update (W_49 -> W_50) from P_49. 1 block x 576 threads.
// ---------------------------------------------------------------------------
__global__ __launch_bounds__(576) void k_iterWfin() {
    GRID_DEP_SYNC();
    __shared__ float sVHt[512];
    __shared__ float sHHt[64];
    int tid = threadIdx.x;
    float s = 0.f;
    {
        const float4* p = (const float4*)&g_partialBuf[1][tid * GRID];
#pragma unroll 8
        for (int b = 0; b < GRID / 4; b++) { float4 v = p[b]; s += (v.x + v.y) + (v.z + v.w); }
    }
    if (tid < 512) sVHt[tid] = s; else sHHt[tid - 512] = s;
    __syncthreads();
    if (tid < 512) {
        int t = tid >> 3, l = tid & 7;
        float den = EPS_F;
#pragma unroll
        for (int j = 0; j < 8; j++) den += g_Wb[0][t * 8 + j] * sHHt[j * 8 + l];
        g_Wfin[tid] = g_Wb[0][tid] * sVHt[tid] / den;
    }
    __syncthreads();
    PDL_TRIGGER();
}

// ---------------------------------------------------------------------------
// K5: fused epilogue + error (proven): grid MUST be 256 x 256
// ---------------------------------------------------------------------------
__global__ __launch_bounds__(256) void k_final(const float* __restrict__ wp1,
                                               const float* __restrict__ wp2,
                                               float* __restrict__ out,
                                               int out_size) {
    GRID_DEP_SYNC();
    __shared__ __align__(16) float sW[512];
    __shared__ __align__(16) float sA[512];
    __shared__ __align__(16) float sP[4096];
    __shared__ float ssum[256];
    __shared__ int sIsLast;
    int tid = threadIdx.x;
    for (int i = tid; i < 512; i += 256) sW[i] = g_Wfin[i];
    for (int i = tid; i < 4096; i += 256) sP[i] = wp2[i];
    __syncthreads();

    {
        int t0 = tid >> 3, l0 = tid & 7;
        float s0 = 0.f;
#pragma unroll 8
        for (int c = 0; c < 64; c++) s0 += wp1[t0 * 64 + c] * sW[c * 8 + l0];
        sA[tid] = s0;
        int i1 = tid + 256;
        int t1 = i1 >> 3, l1 = i1 & 7;
        float s1 = 0.f;
#pragma unroll 8
        for (int c = 0; c < 64; c++) s1 += wp1[t1 * 64 + c] * sW[c * 8 + l1];
        sA[i1] = s1;
    }
    __syncthreads();

    int m = blockIdx.x * 256 + tid;
    float h[8];
#pragma unroll
    for (int l = 0; l < 8; l++) h[l] = g_H[l * MCOLS + m];

    float y[64];
    float err = 0.f;
#pragma unroll
    for (int t = 0; t < 64; t++) {
        const float4* w4 = (const float4*)&sW[t * 8];
        float4 wa = w4[0], wb = w4[1];
        float vh = wa.x * h[0] + wa.y * h[1] + wa.z * h[2] + wa.w * h[3]
                 + wb.x * h[4] + wb.y * h[5] + wb.z * h[6] + wb.w * h[7];
        const float4* a4 = (const float4*)&sA[t * 8];
        float4 aa = a4[0], ab = a4[1];
        float ya = aa.x * h[0] + aa.y * h[1] + aa.z * h[2] + aa.w * h[3]
                 + ab.x * h[4] + ab.y * h[5] + ab.z * h[6] + ab.w * h[7];
        float d = g_V[t * MCOLS + m] - vh;
        err += d * d;
        y[t] = fmaxf(ya, 0.f);
    }

#pragma unroll 1
    for (int t = 0; t < 64; t++) {
        const float4* p4 = (const float4*)&sP[t * 64];
        float o = 0.f;
#pragma unroll
        for (int q = 0; q < 16; q++) {
            float4 w = p4[q];
            o += w.x * y[4 * q] + w.y * y[4 * q + 1] + w.z * y[4 * q + 2] + w.w * y[4 * q + 3];
        }
        out[t * MCOLS + m] = o;
    }

    ssum[tid] = err; __syncthreads();
    for (int s = 128; s; s >>= 1) { if (tid < s) ssum[tid] += ssum[tid + s]; __syncthreads(); }
    if (tid == 0) g_red2[blockIdx.x] = ssum[0];

    // no-wait last-block (proven): 256th arriver computes the error
    __threadfence();
    __syncthreads();
    if (tid == 0) {
        unsigned v = atomicAdd(&g_cntE, 1u);
        sIsLast = (v == 255u);
    }
    __syncthreads();
    if (sIsLast) {
        __threadfence();
        ssum[tid] = __ldcg(&g_red2[tid]);
        __syncthreads();
        for (int s = 128; s; s >>= 1) { if (tid < s) ssum[tid] += ssum[tid + s]; __syncthreads(); }
        if (tid == 0) out[out_size - 1] = sqrtf(ssum[0]);
    }
}

// ---------------------------------------------------------------------------
// Host: PDL launches (graph-capturable)
// ---------------------------------------------------------------------------
template <typename F, typename... Args>
static void launch_pdl(dim3 grid, dim3 block, size_t smem, F func, Args... args) {
    cudaLaunchConfig_t cfg = {};
    cfg.gridDim = grid;
    cfg.blockDim = block;
    cfg.dynamicSmemBytes = smem;
    cudaLaunchAttribute attr[1];
    attr[0].id = cudaLaunchAttributeProgrammaticStreamSerialization;
    attr[0].val.programmaticStreamSerializationAllowed = 1;
    cfg.attrs = attr;
    cfg.numAttrs = 1;
    cudaLaunchKernelEx(&cfg, func, args...);
}

extern "C" void kernel_launch(void* const* d_in, const int* in_sizes, int n_in,
                              void* d_out, int out_size) {
    const float* eps  = (const float*)d_in[0];
    const float* wpre = (const float*)d_in[1];
    const float* bpre = (const float*)d_in[2];
    const float* wp1  = (const float*)d_in[3];
    const float* wp2  = (const float*)d_in[4];
    float* out = (float*)d_out;

    cudaFuncSetAttribute(k_iter, cudaFuncAttributeMaxDynamicSharedMemorySize,
                         ITER_SMEM_BYTES);

    launch_pdl(dim3(256), dim3(256), 0, k_preconv, eps, wpre, bpre);
    launch_pdl(dim3(2048), dim3(256), 0, k_init);
    for (int it = 0; it < NMF_ITERS; it++)
        launch_pdl(dim3(GRID), dim3(IBLK), ITER_SMEM_BYTES, k_iter, it);
    launch_pdl(dim3(1), dim3(576), 0, k_iterWfin);
    launch_pdl(dim3(256), dim3(256), 0, k_final, wp1, wp2, out, out_size);
}

// round 17
// speedup vs baseline: 1.0446x; 1.0446x over previous
#include <cuda_runtime.h>
#include <math.h>
#include <stdint.h>

#define MCOLS 65536
#define TCH   64
#define LRANK 8
#define NMF_ITERS 50
#define EPS_F 1.1920929e-07f
#define GRID  128                 // blocks in k_iter; stride of partials
#define IBLK  512                 // threads per k_iter block

// dynamic smem layout (bytes) for k_iter
//   sHnP  [0, 16384)        4*512 ull
//   sW    [16384, 18432)    512 floats
//   sWtW  [18432, 18688)    64 floats
//   sWtWp [18688, 20736)    512 floats
//   sRed  [20736, 23040)    576 floats
//   sT    [23040, 99072)    576 x 33 floats (transpose-reduce buffer)
#define ITER_SMEM_BYTES 99072

typedef unsigned long long ull;

// ---------------------------------------------------------------------------
// Scratch (no allocations allowed)
// ---------------------------------------------------------------------------
__device__ __align__(16) float g_V[TCH * MCOLS];          // relu(conv), row-major
__device__ __align__(16) float g_H[LRANK * MCOLS];
__device__ __align__(16) float g_Wb[2][TCH * LRANK];      // W parity buffers
__device__ __align__(16) float g_Wfin[TCH * LRANK];       // W_50 for epilogue
__device__ __align__(16) float g_partialBuf[2][576 * GRID];  // [parity][idx][block]
__device__ float g_red[256];
__device__ float g_red2[256];
__device__ unsigned g_cntE;                               // k_final last-block ticket

// PDL intrinsics guards
#if defined(__CUDA_ARCH__) && __CUDA_ARCH__ >= 900
#define GRID_DEP_SYNC() cudaGridDependencySynchronize()
#define PDL_TRIGGER()   cudaTriggerProgrammaticLaunchCompletion()
#else
#define GRID_DEP_SYNC()
#define PDL_TRIGGER()
#endif

// ---------------------------------------------------------------------------
// Packed fp32x2 helpers (per-lane bitwise identical to scalar FFMA)
// ---------------------------------------------------------------------------
__device__ __forceinline__ ull pack2(float lo, float hi) {
    ull r;
    asm("mov.b64 %0, {%1, %2};" : "=l"(r)
        : "r"(__float_as_uint(lo)), "r"(__float_as_uint(hi)));
    return r;
}
__device__ __forceinline__ void unpack2(ull v, float& lo, float& hi) {
    unsigned a, b;
    asm("mov.b64 {%0, %1}, %2;" : "=r"(a), "=r"(b) : "l"(v));
    lo = __uint_as_float(a); hi = __uint_as_float(b);
}
__device__ __forceinline__ ull fma2(ull a, ull b, ull c) {
    ull d;
    asm("fma.rn.f32x2 %0, %1, %2, %3;" : "=l"(d) : "l"(a), "l"(b), "l"(c));
    return d;
}

// ---------------------------------------------------------------------------
// Threefry-2x32 (JAX), 20 rounds
// ---------------------------------------------------------------------------
__device__ __forceinline__ void tf2x32(unsigned k0, unsigned k1,
                                       unsigned x0, unsigned x1,
                                       unsigned& o0, unsigned& o1) {
    unsigned ks2 = k0 ^ k1 ^ 0x1BD11BDAu;
    x0 += k0; x1 += k1;
#define TF_RND(r) { x0 += x1; x1 = (x1 << (r)) | (x1 >> (32 - (r))); x1 ^= x0; }
    TF_RND(13) TF_RND(15) TF_RND(26) TF_RND(6)
    x0 += k1;  x1 += ks2 + 1u;
    TF_RND(17) TF_RND(29) TF_RND(16) TF_RND(24)
    x0 += ks2; x1 += k0 + 2u;
    TF_RND(13) TF_RND(15) TF_RND(26) TF_RND(6)
    x0 += k0;  x1 += k1 + 3u;
    TF_RND(17) TF_RND(29) TF_RND(16) TF_RND(24)
    x0 += k1;  x1 += ks2 + 4u;
    TF_RND(13) TF_RND(15) TF_RND(26) TF_RND(6)
    x0 += ks2; x1 += k0 + 5u;
#undef TF_RND
    o0 = x0; o1 = x1;
}

__device__ __forceinline__ float bits_to_uniform(unsigned b) {
    return __uint_as_float((b >> 9) | 0x3f800000u) - 1.0f;
}

// ---------------------------------------------------------------------------
// K1: Vst = relu(w_pre @ eps + b_pre) + per-block sum   (proven)
// grid MUST be 256 x 256
// ---------------------------------------------------------------------------
__global__ __launch_bounds__(256) void k_preconv(const float* __restrict__ eps,
                                                 const float* __restrict__ wpre,
                                                 const float* __restrict__ bpre) {
    __shared__ __align__(16) float sT[4096];
    __shared__ float sb[64];
    __shared__ float ssum[256];
    int tid = threadIdx.x;
    for (int i = tid; i < 4096; i += 256) {
        int t = i >> 6, c = i & 63;
        sT[c * 64 + t] = wpre[i];
    }
    if (tid < 64) sb[tid] = bpre[tid];
    __syncthreads();

    int m = blockIdx.x * 256 + tid;
    float acc[64];
#pragma unroll
    for (int t = 0; t < 64; t++) acc[t] = sb[t];
#pragma unroll 1
    for (int c = 0; c < 64; c++) {
        float e = eps[c * MCOLS + m];
        const float4* wr = (const float4*)&sT[c * 64];
#pragma unroll
        for (int q = 0; q < 16; q++) {
            float4 w = wr[q];
            acc[4 * q + 0] += w.x * e;
            acc[4 * q + 1] += w.y * e;
            acc[4 * q + 2] += w.z * e;
            acc[4 * q + 3] += w.w * e;
        }
    }
    float ls = 0.f;
#pragma unroll
    for (int t = 0; t < 64; t++) {
        float v = fmaxf(acc[t], 0.f);
        g_V[t * MCOLS + m] = v;
        ls += v;
    }
    ssum[tid] = ls; __syncthreads();
    for (int s = 128; s; s >>= 1) { if (tid < s) ssum[tid] += ssum[tid + s]; __syncthreads(); }
    if (tid == 0) g_red[blockIdx.x] = ssum[0];
    __syncthreads();
    PDL_TRIGGER();
}

// ---------------------------------------------------------------------------
// K2: fused scalar+init (proven). grid MUST be 2048 x 256. W0 -> g_Wb[0].
// ---------------------------------------------------------------------------
__global__ __launch_bounds__(256) void k_init() {
    GRID_DEP_SYNC();
    __shared__ float s[256];
    __shared__ unsigned skeys[4];
    __shared__ float savg;
    int tid = threadIdx.x;
    s[tid] = g_red[tid];
    __syncthreads();
    for (int st = 128; st; st >>= 1) { if (tid < st) s[tid] += s[tid + st]; __syncthreads(); }
    if (tid == 0) {
        float mean = s[0] / (float)(TCH * MCOLS);
        savg = sqrtf(mean / (float)LRANK);
        unsigned o0, o1;
        tf2x32(0u, 0u, 0u, 0u, o0, o1); skeys[0] = o0; skeys[1] = o1;  // kW
        tf2x32(0u, 0u, 0u, 1u, o0, o1); skeys[2] = o0; skeys[3] = o1;  // kH
        if (blockIdx.x == 0) g_cntE = 0u;
    }
    __syncthreads();

    unsigned i = blockIdx.x * 256u + tid;   // < 524288
    float avg = savg;
    unsigned o0, o1;
    tf2x32(skeys[2], skeys[3], 0u, i, o0, o1);
    g_H[i] = avg * bits_to_uniform(o0 ^ o1);
    if (i < TCH * LRANK) {
        tf2x32(skeys[0], skeys[1], 0u, i, o0, o1);
        g_Wb[0][i] = avg * bits_to_uniform(o0 ^ o1);
    }
    __syncthreads();
    PDL_TRIGGER();
}

// ---------------------------------------------------------------------------
// K3: one fused NMF iteration. grid GRID=128 x IBLK=512 (1 col/thread).
//   prologue (it>0): each block redundantly reduces P_{it-1} (exact k_iterW
//     order) and computes W_it; block 0 publishes to g_Wb[(it+1)&1].
//   body: distributed WtW, packed-f32x2 H update, packed-f32x2 partials.
//   tail: SMEM transpose reduction (no shuffles): each thread stores its 40
//     lane-local sums to sT[o][lane] (stride 33, conflict-free), sync, then
//     thread o sums 32 lanes sequentially and writes g_partial[o*GRID+bid].
// ---------------------------------------------------------------------------
__global__ __launch_bounds__(IBLK, 1) void k_iter(int it) {
    GRID_DEP_SYNC();
    extern __shared__ __align__(16) char smraw[];
    ull*   sHnP  = (ull*)smraw;                        // 4 x 512
    float* sW    = (float*)(smraw + 16384);            // 512
    float* sWtW  = (float*)(smraw + 18432);            // 64
    float* sWtWp = (float*)(smraw + 18688);            // 512
    float* sRed  = (float*)(smraw + 20736);            // 576
    float* sT    = (float*)(smraw + 23040);            // 576 x 33

    int tid = threadIdx.x, lane = tid & 31, warp = tid >> 5;
    int bid = blockIdx.x;
    int m = bid * IBLK + tid;

    // hoist: H loads independent of W/partials
    float h[8];
#pragma unroll
    for (int l = 0; l < 8; l++) h[l] = g_H[l * MCOLS + m];

    if (it > 0) {
        const float* __restrict__ P = g_partialBuf[(it + 1) & 1];  // P_{it-1}
        for (int o = tid; o < 576; o += IBLK) {
            const float4* p = (const float4*)&P[o * GRID];
            float s = 0.f;
#pragma unroll 8
            for (int b = 0; b < GRID / 4; b++) { float4 v = p[b]; s += (v.x + v.y) + (v.z + v.w); }
            sRed[o] = s;
        }
        __syncthreads();
        const float* __restrict__ Wold = g_Wb[it & 1];
        {
            int t0 = tid >> 3, l0 = tid & 7;
            float den = EPS_F;
#pragma unroll
            for (int j = 0; j < 8; j++) den += Wold[t0 * 8 + j] * sRed[512 + j * 8 + l0];
            float nw = Wold[tid] * sRed[tid] / den;
            sW[tid] = nw;
            if (bid == 0) g_Wb[(it + 1) & 1][tid] = nw;
        }
    } else {
        sW[tid] = g_Wb[0][tid];
        if (bid == 0) g_Wb[1][tid] = g_Wb[0][tid];
    }
    __syncthreads();

    // --- distributed WtW partials (8-term dot per thread) ---
    {
        int lj = tid & 63, oct = tid >> 6;            // oct in [0,8)
        int l = lj >> 3, j = lj & 7;
        float s = 0.f;
#pragma unroll
        for (int tt = 0; tt < 8; tt++) {
            int t = oct * 8 + tt;
            s += sW[t * 8 + l] * sW[t * 8 + j];
        }
        sWtWp[lj * 8 + oct] = s;
    }

    // phase 1: wtv = W^T v_col, packed pairs (bitwise == scalar order)
    ull wtvP[4] = {0ull, 0ull, 0ull, 0ull};
    const ull* sW2 = (const ull*)sW;                  // pairs (l, l+1) per t
#pragma unroll 1
    for (int tb = 0; tb < 64; tb += 16) {
        float v[16];
#pragma unroll
        for (int i = 0; i < 16; i++) v[i] = g_V[(tb + i) * MCOLS + m];
#pragma unroll
        for (int i = 0; i < 16; i++) {
            ull vp = pack2(v[i], v[i]);
            int t = tb + i;
            wtvP[0] = fma2(sW2[t * 4 + 0], vp, wtvP[0]);
            wtvP[1] = fma2(sW2[t * 4 + 1], vp, wtvP[1]);
            wtvP[2] = fma2(sW2[t * 4 + 2], vp, wtvP[2]);
            wtvP[3] = fma2(sW2[t * 4 + 3], vp, wtvP[3]);
        }
    }
    float wtv[8];
#pragma unroll
    for (int p = 0; p < 4; p++) unpack2(wtvP[p], wtv[2 * p], wtv[2 * p + 1]);
    __syncthreads();

    // finalize WtW (64 threads, sequential octant sum)
    if (tid < 64) {
        float s = 0.f;
#pragma unroll
        for (int o = 0; o < 8; o++) s += sWtWp[tid * 8 + o];
        sWtW[tid] = s;
    }
    __syncthreads();

    // H update (scalar den, proven order)
    float hn[8];
#pragma unroll
    for (int l = 0; l < 8; l++) {
        const float4* q4 = (const float4*)&sWtW[l * 8];
        float4 qa = q4[0], qb = q4[1];
        float den = EPS_F
            + qa.x * h[0] + qa.y * h[1] + qa.z * h[2] + qa.w * h[3]
            + qb.x * h[4] + qb.y * h[5] + qb.z * h[6] + qb.w * h[7];
        hn[l] = h[l] * wtv[l] / den;
        g_H[l * MCOLS + m] = hn[l];
    }
#pragma unroll
    for (int p = 0; p < 4; p++) sHnP[p * IBLK + tid] = pack2(hn[2 * p], hn[2 * p + 1]);
    __syncthreads();

    // --- phase 2: packed partial VHt (warp: rows 4w..4w+3) + HHt (warps 0-7) ---
    ull accP[4][4], acchP[4];
#pragma unroll
    for (int a = 0; a < 4; a++)
#pragma unroll
        for (int p = 0; p < 4; p++) accP[a][p] = 0ull;
#pragma unroll
    for (int p = 0; p < 4; p++) acchP[p] = 0ull;

    const float* sHnF = (const float*)sHnP;
#pragma unroll 2
    for (int gg = 0; gg < 16; gg++) {
        int mm = gg * 32 + lane;
        ull hlP0 = sHnP[0 * IBLK + mm];
        ull hlP1 = sHnP[1 * IBLK + mm];
        ull hlP2 = sHnP[2 * IBLK + mm];
        ull hlP3 = sHnP[3 * IBLK + mm];
        float v0 = g_V[(warp * 4 + 0) * MCOLS + bid * IBLK + mm];
        float v1 = g_V[(warp * 4 + 1) * MCOLS + bid * IBLK + mm];
        float v2 = g_V[(warp * 4 + 2) * MCOLS + bid * IBLK + mm];
        float v3 = g_V[(warp * 4 + 3) * MCOLS + bid * IBLK + mm];
        ull vp0 = pack2(v0, v0), vp1 = pack2(v1, v1);
        ull vp2 = pack2(v2, v2), vp3 = pack2(v3, v3);
        accP[0][0] = fma2(vp0, hlP0, accP[0][0]);
        accP[0][1] = fma2(vp0, hlP1, accP[0][1]);
        accP[0][2] = fma2(vp0, hlP2, accP[0][2]);
        accP[0][3] = fma2(vp0, hlP3, accP[0][3]);
        accP[1][0] = fma2(vp1, hlP0, accP[1][0]);
        accP[1][1] = fma2(vp1, hlP1, accP[1][1]);
        accP[1][2] = fma2(vp1, hlP2, accP[1][2]);
        accP[1][3] = fma2(vp1, hlP3, accP[1][3]);
        accP[2][0] = fma2(vp2, hlP0, accP[2][0]);
        accP[2][1] = fma2(vp2, hlP1, accP[2][1]);
        accP[2][2] = fma2(vp2, hlP2, accP[2][2]);
        accP[2][3] = fma2(vp2, hlP3, accP[2][3]);
        accP[3][0] = fma2(vp3, hlP0, accP[3][0]);
        accP[3][1] = fma2(vp3, hlP1, accP[3][1]);
        accP[3][2] = fma2(vp3, hlP2, accP[3][2]);
        accP[3][3] = fma2(vp3, hlP3, accP[3][3]);
        if (warp < 8) {
            float hw = sHnF[((warp >> 1) * IBLK + mm) * 2 + (warp & 1)];
            ull hwp = pack2(hw, hw);
            acchP[0] = fma2(hwp, hlP0, acchP[0]);
            acchP[1] = fma2(hwp, hlP1, acchP[1]);
            acchP[2] = fma2(hwp, hlP2, acchP[2]);
            acchP[3] = fma2(hwp, hlP3, acchP[3]);
        }
    }

    // --- tail: SMEM transpose reduction (replaces shuffle butterfly) ---
#pragma unroll
    for (int a = 0; a < 4; a++)
#pragma unroll
        for (int p = 0; p < 4; p++) {
            float lo, hi;
            unpack2(accP[a][p], lo, hi);
            int o = (warp * 4 + a) * 8 + 2 * p;
            sT[o * 33 + lane] = lo;
            sT[(o + 1) * 33 + lane] = hi;
        }
    if (warp < 8) {
#pragma unroll
        for (int p = 0; p < 4; p++) {
            float lo, hi;
            unpack2(acchP[p], lo, hi);
            int o = 512 + warp * 8 + 2 * p;
            sT[o * 33 + lane] = lo;
            sT[(o + 1) * 33 + lane] = hi;
        }
    }
    __syncthreads();

    // thread o reduces its output's 32 lanes sequentially; writes partial
    float* __restrict__ pbufW = g_partialBuf[it & 1];
    {
        float s = 0.f;
#pragma unroll
        for (int k = 0; k < 32; k++) s += sT[tid * 33 + k];
        pbufW[tid * GRID + bid] = s;
    }
    if (tid < 64) {
        float s = 0.f;
#pragma unroll
        for (int k = 0; k < 32; k++) s += sT[(512 + tid) * 33 + k];
        pbufW[(512 + tid) * GRID + bid] = s;
    }
    __syncthreads();
    PDL_TRIGGER();
}

// ---------------------------------------------------------------------------
// K4: final W update (W_49 -> W_50) from P_49. 1 block x 576 threads.
// ---------------------------------------------------------------------------
__global__ __launch_bounds__(576) void k_iterWfin() {
    GRID_DEP_SYNC();
    __shared__ float sVHt[512];
    __shared__ float sHHt[64];
    int tid = threadIdx.x;
    float s = 0.f;
    {
        const float4* p = (const float4*)&g_partialBuf[1][tid * GRID];
#pragma unroll 8
        for (int b = 0; b < GRID / 4; b++) { float4 v = p[b]; s += (v.x + v.y) + (v.z + v.w); }
    }
    if (tid < 512) sVHt[tid] = s; else sHHt[tid - 512] = s;
    __syncthreads();
    if (tid < 512) {
        int t = tid >> 3, l = tid & 7;
        float den = EPS_F;
#pragma unroll
        for (int j = 0; j < 8; j++) den += g_Wb[0][t * 8 + j] * sHHt[j * 8 + l];
        g_Wfin[tid] = g_Wb[0][tid] * sVHt[tid] / den;
    }
    __syncthreads();
    PDL_TRIGGER();
}

// ---------------------------------------------------------------------------
// K5: fused epilogue + error (proven): grid MUST be 256 x 256
// ---------------------------------------------------------------------------
__global__ __launch_bounds__(256) void k_final(const float* __restrict__ wp1,
                                               const float* __restrict__ wp2,
                                               float* __restrict__ out,
                                               int out_size) {
    GRID_DEP_SYNC();
    __shared__ __align__(16) float sW[512];
    __shared__ __align__(16) float sA[512];
    __shared__ __align__(16) float sP[4096];
    __shared__ float ssum[256];
    __shared__ int sIsLast;
    int tid = threadIdx.x;
    for (int i = tid; i < 512; i += 256) sW[i] = g_Wfin[i];
    for (int i = tid; i < 4096; i += 256) sP[i] = wp2[i];
    __syncthreads();

    {
        int t0 = tid >> 3, l0 = tid & 7;
        float s0 = 0.f;
#pragma unroll 8
        for (int c = 0; c < 64; c++) s0 += wp1[t0 * 64 + c] * sW[c * 8 + l0];
        sA[tid] = s0;
        int i1 = tid + 256;
        int t1 = i1 >> 3, l1 = i1 & 7;
        float s1 = 0.f;
#pragma unroll 8
        for (int c = 0; c < 64; c++) s1 += wp1[t1 * 64 + c] * sW[c * 8 + l1];
        sA[i1] = s1;
    }
    __syncthreads();

    int m = blockIdx.x * 256 + tid;
    float h[8];
#pragma unroll
    for (int l = 0; l < 8; l++) h[l] = g_H[l * MCOLS + m];

    float y[64];
    float err = 0.f;
#pragma unroll
    for (int t = 0; t < 64; t++) {
        const float4* w4 = (const float4*)&sW[t * 8];
        float4 wa = w4[0], wb = w4[1];
        float vh = wa.x * h[0] + wa.y * h[1] + wa.z * h[2] + wa.w * h[3]
                 + wb.x * h[4] + wb.y * h[5] + wb.z * h[6] + wb.w * h[7];
        const float4* a4 = (const float4*)&sA[t * 8];
        float4 aa = a4[0], ab = a4[1];
        float ya = aa.x * h[0] + aa.y * h[1] + aa.z * h[2] + aa.w * h[3]
                 + ab.x * h[4] + ab.y * h[5] + ab.z * h[6] + ab.w * h[7];
        float d = g_V[t * MCOLS + m] - vh;
        err += d * d;
        y[t] = fmaxf(ya, 0.f);
    }

#pragma unroll 1
    for (int t = 0; t < 64; t++) {
        const float4* p4 = (const float4*)&sP[t * 64];
        float o = 0.f;
#pragma unroll
        for (int q = 0; q < 16; q++) {
            float4 w = p4[q];
            o += w.x * y[4 * q] + w.y * y[4 * q + 1] + w.z * y[4 * q + 2] + w.w * y[4 * q + 3];
        }
        out[t * MCOLS + m] = o;
    }

    ssum[tid] = err; __syncthreads();
    for (int s = 128; s; s >>= 1) { if (tid < s) ssum[tid] += ssum[tid + s]; __syncthreads(); }
    if (tid == 0) g_red2[blockIdx.x] = ssum[0];

    // no-wait last-block (proven): 256th arriver computes the error
    __threadfence();
    __syncthreads();
    if (tid == 0) {
        unsigned v = atomicAdd(&g_cntE, 1u);
        sIsLast = (v == 255u);
    }
    __syncthreads();
    if (sIsLast) {
        __threadfence();
        ssum[tid] = __ldcg(&g_red2[tid]);
        __syncthreads();
        for (int s = 128; s; s >>= 1) { if (tid < s) ssum[tid] += ssum[tid + s]; __syncthreads(); }
        if (tid == 0) out[out_size - 1] = sqrtf(ssum[0]);
    }
}

// ---------------------------------------------------------------------------
// Host: PDL launches (graph-capturable)
// ---------------------------------------------------------------------------
template <typename F, typename... Args>
static void launch_pdl(dim3 grid, dim3 block, size_t smem, F func, Args... args) {
    cudaLaunchConfig_t cfg = {};
    cfg.gridDim = grid;
    cfg.blockDim = block;
    cfg.dynamicSmemBytes = smem;
    cudaLaunchAttribute attr[1];
    attr[0].id = cudaLaunchAttributeProgrammaticStreamSerialization;
    attr[0].val.programmaticStreamSerializationAllowed = 1;
    cfg.attrs = attr;
    cfg.numAttrs = 1;
    cudaLaunchKernelEx(&cfg, func, args...);
}

extern "C" void kernel_launch(void* const* d_in, const int* in_sizes, int n_in,
                              void* d_out, int out_size) {
    const float* eps  = (const float*)d_in[0];
    const float* wpre = (const float*)d_in[1];
    const float* bpre = (const float*)d_in[2];
    const float* wp1  = (const float*)d_in[3];
    const float* wp2  = (const float*)d_in[4];
    float* out = (float*)d_out;

    cudaFuncSetAttribute(k_iter, cudaFuncAttributeMaxDynamicSharedMemorySize,
                         ITER_SMEM_BYTES);

    launch_pdl(dim3(256), dim3(256), 0, k_preconv, eps, wpre, bpre);
    launch_pdl(dim3(2048), dim3(256), 0, k_init);
    for (int it = 0; it < NMF_ITERS; it++)
        launch_pdl(dim3(GRID), dim3(IBLK), ITER_SMEM_BYTES, k_iter, it);
    launch_pdl(dim3(1), dim3(576), 0, k_iterWfin);
    launch_pdl(dim3(256), dim3(256), 0, k_final, wp1, wp2, out, out_size);
}